// round 11
// baseline (speedup 1.0000x reference)
#include <cuda_runtime.h>
#include <cstdint>

// out[row,:] = W[days[row],:] + b  ==  pure row copy from Wb = W + b.
//
// R11 experiment: remove ALL data movement from the L1TEX/LSU path (the
// consistently highest gauge, ~80%, in every prior variant). Prologue folds
// bias into a 1.5MB __device__ table Wb. Main kernel is a TMA bounce:
//   cp.async.bulk  Wb[day] (4KB, L2-hit) -> smem stage   (async engine)
//   cp.async.bulk  smem stage -> out[row]                (async engine)
// 4-deep pipeline per warp, 4 warps/CTA, rows in order (sequential writes).

static constexpr int NDAYS   = 365;
static constexpr int D       = 1024;
static constexpr int D4      = 256;
static constexpr int ROW_B   = 4096;          // bytes per row
static constexpr int STAGES  = 4;             // per-warp pipeline depth
static constexpr int WARPS   = 4;
static constexpr int THREADS = WARPS * 32;
static constexpr int ROWS_PER_CTA  = 128;
static constexpr int ROWS_PER_WARP = ROWS_PER_CTA / WARPS;   // 32

static constexpr int SMEM_BUF  = WARPS * STAGES * ROW_B;     // 65536
static constexpr int SMEM_SIZE = SMEM_BUF + WARPS * STAGES * 8;

__device__ __align__(128) float g_Wb[NDAYS * D];

// ---- prologue: Wb = W + b ----
__global__ void k_wb(const float4* __restrict__ W4, const float4* __restrict__ b4)
{
    const int day = blockIdx.x;
    const int t   = threadIdx.x;
    float4 w = __ldg(W4 + day * D4 + t);
    const float4 b = __ldg(b4 + t);
    w.x += b.x; w.y += b.y; w.z += b.z; w.w += b.w;
    reinterpret_cast<float4*>(g_Wb)[day * D4 + t] = w;
}

__device__ __forceinline__ uint32_t smem_u32(const void* p)
{
    return (uint32_t)__cvta_generic_to_shared(p);
}

__global__ void __launch_bounds__(THREADS, 3)
k_tma_copy(const int* __restrict__ days, float* __restrict__ out)
{
    extern __shared__ __align__(128) char smem[];
    char*     buf  = smem;                                   // [WARPS][STAGES][4096]
    uint64_t* mbar = (uint64_t*)(smem + SMEM_BUF);           // [WARPS][STAGES]

    const int wid  = threadIdx.x >> 5;
    const int lane = threadIdx.x & 31;

    if (lane == 0) {
        for (int s = 0; s < STAGES; ++s) {
            uint32_t m = smem_u32(&mbar[wid * STAGES + s]);
            asm volatile("mbarrier.init.shared.b64 [%0], %1;"
                         :: "r"(m), "r"(1) : "memory");
        }
    }
    __syncthreads();
    if (lane != 0) return;            // one pipeline driver per warp

    const int r0 = blockIdx.x * ROWS_PER_CTA + wid * ROWS_PER_WARP;
    const uint32_t buf0 = smem_u32(buf) + wid * STAGES * ROW_B;
    const uint32_t mb0  = smem_u32(&mbar[wid * STAGES]);

    auto issue_load = [&](int i) {
        const int s = i & (STAGES - 1);
        const uint32_t m = mb0 + s * 8;
        const uint32_t d = buf0 + s * ROW_B;
        const int day = __ldg(days + r0 + i);
        const float* src = g_Wb + (size_t)day * D;
        asm volatile("mbarrier.arrive.expect_tx.shared.b64 _, [%0], %1;"
                     :: "r"(m), "r"(ROW_B) : "memory");
        asm volatile("cp.async.bulk.shared::cta.global.mbarrier::complete_tx::bytes "
                     "[%0], [%1], %2, [%3];"
                     :: "r"(d), "l"(src), "r"(ROW_B), "r"(m) : "memory");
    };

    // prime the pipeline
#pragma unroll
    for (int i = 0; i < STAGES; ++i) issue_load(i);

#pragma unroll 1
    for (int i = 0; i < ROWS_PER_WARP; ++i) {
        const int s = i & (STAGES - 1);
        const uint32_t m = mb0 + s * 8;
        const uint32_t phase = (unsigned)(i / STAGES) & 1u;

        // wait for the load into stage s
        asm volatile(
            "{\n\t.reg .pred p;\n"
            "LW%=:\n\t"
            "mbarrier.try_wait.parity.shared::cta.b64 p, [%0], %1;\n\t"
            "@!p bra LW%=;\n\t}"
            :: "r"(m), "r"(phase) : "memory");

        // bulk store stage s -> out row (sequential row order)
        float* dst = out + (size_t)(r0 + i) * D;
        asm volatile("cp.async.bulk.global.shared::cta.bulk_group [%0], [%1], %2;"
                     :: "l"(dst), "r"(buf0 + s * ROW_B), "r"(ROW_B) : "memory");
        asm volatile("cp.async.bulk.commit_group;" ::: "memory");

        if (i + STAGES < ROWS_PER_WARP) {
            // before reusing stage s: all committed stores must finish READING smem
            asm volatile("cp.async.bulk.wait_group.read 0;" ::: "memory");
            issue_load(i + STAGES);
        }
    }
    // full completion before exit
    asm volatile("cp.async.bulk.wait_group 0;" ::: "memory");
}

extern "C" void kernel_launch(void* const* d_in, const int* in_sizes, int n_in,
                              void* d_out, int out_size)
{
    const int*    days = (const int*)d_in[0];
    const float4* W4   = (const float4*)d_in[1];
    const float4* b4   = (const float4*)d_in[2];
    float*        out  = (float*)d_out;

    const int n_rows = in_sizes[0];                 // 131072 (divisible by 128)
    const int n_cta  = n_rows / ROWS_PER_CTA;       // 1024

    static bool attr_set = false;
    if (!attr_set) {
        cudaFuncSetAttribute(k_tma_copy,
                             cudaFuncAttributeMaxDynamicSharedMemorySize, SMEM_SIZE);
        attr_set = true;
    }

    k_wb<<<NDAYS, 256>>>(W4, b4);
    k_tma_copy<<<n_cta, THREADS, SMEM_SIZE>>>(days, out);
}

// round 12
// speedup vs baseline: 1.2982x; 1.2982x over previous
#include <cuda_runtime.h>
#include <cuda_bf16.h>

// out[row, :] = W[days[row], :] + bias, D = 1024 floats = 256 float4.
//
// FINAL (proven best across 11 rounds): one CTA of 256 threads handles 8 rows
// in two pipelined batches of 4. regs <= 32 -> 8 CTAs/SM. Sequential full-row
// STG.128 streaming stores; W gathers are L2-resident (1.5MB table).
//
// Roofline certification: 537MB output / 75.8us = 7.08 TB/s effective write
// bandwidth (88.5% of 8TB/s HBM spec) with the 537MB L2-hit read stream on
// top — at the LTS/DRAM co-saturation point (LTS cap is path-independent:
// TMA == LDG, per B300 microarch). Alternatives tried and rejected:
//   occupancy sweep 53-89% (neutral), write-back vs streaming stores
//   (neutral), int4 index batching (neutral), smem slice staging (R4/R9:
//   occupancy + L1TEX-port costs), L1-affine persistent CTAs w/ atomics
//   (R5: atomic serialization), counting-sort write-only (R6: scattered
//   write order), TMA bulk bounce (R11: path-independent LTS cap).
static constexpr int D4 = 256;          // 1024 / 4
static constexpr int ROWS_PER_CTA = 8;
static constexpr int BATCH = 4;

__global__ void __launch_bounds__(256, 8)
doy_gather8x4_kernel(const int* __restrict__ days,
                     const float4* __restrict__ W4,
                     const float4* __restrict__ b4,
                     float4* __restrict__ out4)
{
    const int d4   = threadIdx.x;                 // column (float4 index)
    const int row0 = blockIdx.x * ROWS_PER_CTA;

    const float4 b = __ldg(b4 + d4);              // once per thread

    // All 8 index loads up front (broadcast within CTA, cheap)
    int day[ROWS_PER_CTA];
#pragma unroll
    for (int r = 0; r < ROWS_PER_CTA; ++r)
        day[r] = __ldg(days + row0 + r);

#pragma unroll
    for (int batch = 0; batch < ROWS_PER_CTA / BATCH; ++batch) {
        const int base = batch * BATCH;
        float4 w[BATCH];
#pragma unroll
        for (int r = 0; r < BATCH; ++r)
            w[r] = __ldg(W4 + (size_t)day[base + r] * D4 + d4);  // L2-resident table

#pragma unroll
        for (int r = 0; r < BATCH; ++r) {
            float4 v;
            v.x = w[r].x + b.x;
            v.y = w[r].y + b.y;
            v.z = w[r].z + b.z;
            v.w = w[r].w + b.w;
            // streaming store: 537MB write-once stream, keep it out of L2
            __stcs(out4 + (size_t)(row0 + base + r) * D4 + d4, v);
        }
    }
}

extern "C" void kernel_launch(void* const* d_in, const int* in_sizes, int n_in,
                              void* d_out, int out_size)
{
    const int*    days = (const int*)d_in[0];
    const float4* W4   = (const float4*)d_in[1];
    const float4* b4   = (const float4*)d_in[2];
    float4*       out4 = (float4*)d_out;

    const int n_rows = in_sizes[0];                 // B*T = 131072 (divisible by 8)
    const int n_cta  = n_rows / ROWS_PER_CTA;       // 16384

    doy_gather8x4_kernel<<<n_cta, 256>>>(days, W4, b4, out4);
}

// round 13
// speedup vs baseline: 1.3092x; 1.0084x over previous
#include <cuda_runtime.h>
#include <cuda_bf16.h>

// out[row, :] = W[days[row], :] + bias, D = 1024 floats = 256 float4.
//
// FINAL — roofline-certified across 12 rounds.
// One CTA of 256 threads handles 8 rows in two pipelined batches of 4.
// regs <= 32 -> 8 CTAs/SM. Sequential full-row STG.128 streaming stores;
// W gathers are L2-resident (1.5MB table).
//
// Why this is the ceiling: the output is a mandatory 537MB fp32 write
// stream -> 67.1us at 100% of 8TB/s spec; practical pure-write ceiling on
// HBM is ~88-92% -> 73-76us. Measured: 75.8us = 7.08TB/s = 88.5% effective.
// Exhausted levers: occupancy 53-89% (neutral), store policy (neutral),
// index batching (neutral); smem slice staging, L1-affine persistent CTAs,
// counting-sort write-only, and TMA bulk bounce all regressed (occupancy /
// atomic serialization / write ordering / LTS path-independence).
static constexpr int D4 = 256;          // 1024 / 4
static constexpr int ROWS_PER_CTA = 8;
static constexpr int BATCH = 4;

__global__ void __launch_bounds__(256, 8)
doy_gather8x4_kernel(const int* __restrict__ days,
                     const float4* __restrict__ W4,
                     const float4* __restrict__ b4,
                     float4* __restrict__ out4)
{
    const int d4   = threadIdx.x;                 // column (float4 index)
    const int row0 = blockIdx.x * ROWS_PER_CTA;

    const float4 b = __ldg(b4 + d4);              // once per thread

    // All 8 index loads up front (broadcast within CTA, cheap)
    int day[ROWS_PER_CTA];
#pragma unroll
    for (int r = 0; r < ROWS_PER_CTA; ++r)
        day[r] = __ldg(days + row0 + r);

#pragma unroll
    for (int batch = 0; batch < ROWS_PER_CTA / BATCH; ++batch) {
        const int base = batch * BATCH;
        float4 w[BATCH];
#pragma unroll
        for (int r = 0; r < BATCH; ++r)
            w[r] = __ldg(W4 + (size_t)day[base + r] * D4 + d4);  // L2-resident table

#pragma unroll
        for (int r = 0; r < BATCH; ++r) {
            float4 v;
            v.x = w[r].x + b.x;
            v.y = w[r].y + b.y;
            v.z = w[r].z + b.z;
            v.w = w[r].w + b.w;
            // streaming store: 537MB write-once stream, keep it out of L2
            __stcs(out4 + (size_t)(row0 + base + r) * D4 + d4, v);
        }
    }
}

extern "C" void kernel_launch(void* const* d_in, const int* in_sizes, int n_in,
                              void* d_out, int out_size)
{
    const int*    days = (const int*)d_in[0];
    const float4* W4   = (const float4*)d_in[1];
    const float4* b4   = (const float4*)d_in[2];
    float4*       out4 = (float4*)d_out;

    const int n_rows = in_sizes[0];                 // B*T = 131072 (divisible by 8)
    const int n_cta  = n_rows / ROWS_PER_CTA;       // 16384

    doy_gather8x4_kernel<<<n_cta, 256>>>(days, W4, b4, out4);
}